// round 11
// baseline (speedup 1.0000x reference)
#include <cuda_runtime.h>
#include <cuda_fp16.h>
#include <cstdint>

// Problem constants
#define BB 2
#define TT 2048
#define CC 1024
#define HH 16
#define HD 64

// Scratch (no cudaMalloc). All fp16 where consumed by mma.
__device__ __align__(256) __half g_q[BB * HH * TT * HD];
__device__ __align__(256) __half g_k[BB * HH * TT * HD];
__device__ __align__(256) __half g_v[BB * HH * TT * HD];
__device__ __align__(256) __half g_y[BB * TT * CC];
__device__ __align__(256) __half g_xr[BB * TT * CC];
__device__ __align__(256) __half g_war[3 * CC * CC];
__device__ __align__(256) __half g_wpr[CC * CC];

// ---------------------------------------------------------------------------
// helpers
// ---------------------------------------------------------------------------
__device__ __forceinline__ uint32_t packh2(float lo, float hi) {
    __half2 h = __floats2half2_rn(lo, hi);
    return *reinterpret_cast<uint32_t*>(&h);
}

__device__ __forceinline__ void mma16(float* c, uint32_t a0, uint32_t a1,
                                      uint32_t a2, uint32_t a3,
                                      uint32_t b0, uint32_t b1) {
    asm volatile(
        "mma.sync.aligned.m16n8k16.row.col.f32.f16.f16.f32 "
        "{%0,%1,%2,%3}, {%4,%5,%6,%7}, {%8,%9}, {%0,%1,%2,%3};"
        : "+f"(c[0]), "+f"(c[1]), "+f"(c[2]), "+f"(c[3])
        : "r"(a0), "r"(a1), "r"(a2), "r"(a3), "r"(b0), "r"(b1));
}

__device__ __forceinline__ void ldm4(uint32_t& r0, uint32_t& r1, uint32_t& r2,
                                     uint32_t& r3, uint32_t a) {
    asm volatile("ldmatrix.sync.aligned.m8n8.x4.shared.b16 {%0,%1,%2,%3}, [%4];"
                 : "=r"(r0), "=r"(r1), "=r"(r2), "=r"(r3) : "r"(a));
}
__device__ __forceinline__ void ldm4t(uint32_t& r0, uint32_t& r1, uint32_t& r2,
                                      uint32_t& r3, uint32_t a) {
    asm volatile("ldmatrix.sync.aligned.m8n8.x4.trans.shared.b16 {%0,%1,%2,%3}, [%4];"
                 : "=r"(r0), "=r"(r1), "=r"(r2), "=r"(r3) : "r"(a));
}

__device__ __forceinline__ void cpa16(uint32_t dst, const void* src) {
    asm volatile("cp.async.cg.shared.global [%0], [%1], 16;" :: "r"(dst), "l"(src));
}
__device__ __forceinline__ void cp_commit() {
    asm volatile("cp.async.commit_group;");
}
template <int N>
__device__ __forceinline__ void cp_wait() {
    asm volatile("cp.async.wait_group %0;" :: "n"(N));
}

__device__ __forceinline__ uint32_t s2u(const void* p) {
    return (uint32_t)__cvta_generic_to_shared(p);
}

// XOR swizzle: 128B rows of 8 x 16B chunks; chunk c of row m lives at c^(m&7)
__device__ __forceinline__ uint32_t swz(int m, int c) {
    return (uint32_t)(m * 128 + ((c ^ (m & 7)) << 4));
}

// ---------------------------------------------------------------------------
// prep kernels
// ---------------------------------------------------------------------------
__global__ void prep_x(const float* __restrict__ x) {
    const int i = blockIdx.x * blockDim.x + threadIdx.x;
    const float4 v = *(const float4*)(x + i * 4);
    __half2* p = (__half2*)(g_xr + i * 4);
    p[0] = __floats2half2_rn(v.x, v.y);
    p[1] = __floats2half2_rn(v.z, v.w);
}

// W [1024 x Nc] row-major f32 -> Wt [Nc x 1024] half
__global__ void prep_w(const float* __restrict__ W, int Nc, int which) {
    __shared__ float t[32][33];
    __half* Wt = which ? g_wpr : g_war;
    const int n0 = blockIdx.x * 32, k0 = blockIdx.y * 32;
    const int tx = threadIdx.x, ty0 = threadIdx.y;
#pragma unroll
    for (int i = 0; i < 4; ++i) {
        const int ty = ty0 + i * 8;
        t[ty][tx] = W[(size_t)(k0 + ty) * Nc + n0 + tx];
    }
    __syncthreads();
#pragma unroll
    for (int i = 0; i < 4; ++i) {
        const int ty = ty0 + i * 8;
        Wt[(size_t)(n0 + ty) * 1024 + k0 + tx] = __float2half(t[tx][ty]);
    }
}

// ---------------------------------------------------------------------------
// GEMM: C[M,N] = A[M,1024] @ W[1024,N] + bias  (fp16 mma m16n8k16, fp32 acc)
//   MODE 0: A=g_xr, Wt=g_war, scatter half q/k/v (q scaled 0.125)
//   MODE 1: A=g_y,  Wt=g_wpr, out full fp32
// BM=128, BN=256, BK=64. 256 threads = 8 warps (2m x 4n), WARP TILE 64x64.
// 3-stage cp.async ring, one __syncthreads per k-tile, swizzled 128B rows.
// smem: 3 stages x (A 16384 + B 32768) = 147456 B.  1 CTA/SM.
// ---------------------------------------------------------------------------
template <int MODE, int NW>
__global__ __launch_bounds__(256, 1) void gemm_mma(const float* __restrict__ bias,
                                                   float* __restrict__ out)
{
    extern __shared__ __align__(16) char smem[];
    const uint32_t sb = s2u(smem);

    const __half* A  = (MODE == 0) ? g_xr : g_y;
    const __half* Wt = (MODE == 0) ? g_war : g_wpr;

    const int tid = threadIdx.x;
    const int lane = tid & 31;
    const int g = lane >> 2, t4 = lane & 3;
    const int w = tid >> 5;
    const int wm = w & 1, wn = w >> 1;
    const int row0 = blockIdx.y * 128, col0 = blockIdx.x * 256;

    auto issue = [&](int kt, int st) {
        const uint32_t base = sb + st * 49152;
#pragma unroll
        for (int r = 0; r < 4; ++r) {  // A: 128 rows x 8 chunks
            const int idx = tid + r * 256;
            const int m = idx >> 3, c = idx & 7;
            cpa16(base + swz(m, c), A + (size_t)(row0 + m) * 1024 + kt * 64 + c * 8);
        }
#pragma unroll
        for (int r = 0; r < 8; ++r) {  // B: 256 rows x 8 chunks
            const int idx = tid + r * 256;
            const int n = idx >> 3, c = idx & 7;
            cpa16(base + 16384 + swz(n, c),
                  Wt + (size_t)(col0 + n) * 1024 + kt * 64 + c * 8);
        }
        cp_commit();
    };

    float acc[4][8][4];
#pragma unroll
    for (int mi = 0; mi < 4; ++mi)
#pragma unroll
        for (int ni = 0; ni < 8; ++ni)
#pragma unroll
            for (int j = 0; j < 4; ++j) acc[mi][ni][j] = 0.0f;

    // ldmatrix lane row/chunk decomposition
    const int ar = wm * 64 + (lane & 15);                      // + mi*16
    const int abit = lane >> 4;                                // chunk low bit
    const int br = wn * 64 + (lane & 7) + ((lane >> 4) << 3);  // + np*16
    const int bbit = (lane >> 3) & 1;

    issue(0, 0);
    issue(1, 1);
    for (int kt = 0; kt < 16; ++kt) {
        if (kt + 1 < 16) cp_wait<1>(); else cp_wait<0>();
        __syncthreads();
        if (kt + 2 < 16) issue(kt + 2, (kt + 2) % 3);
        const uint32_t a_s = sb + (kt % 3) * 49152;
        const uint32_t b_s = a_s + 16384;
#pragma unroll
        for (int ks = 0; ks < 4; ++ks) {
            uint32_t a[4][4];
#pragma unroll
            for (int mi = 0; mi < 4; ++mi)
                ldm4(a[mi][0], a[mi][1], a[mi][2], a[mi][3],
                     a_s + swz(ar + mi * 16, 2 * ks + abit));
            uint32_t b[8][2];
#pragma unroll
            for (int np = 0; np < 4; ++np)
                ldm4(b[2 * np][0], b[2 * np][1], b[2 * np + 1][0], b[2 * np + 1][1],
                     b_s + swz(br + np * 16, 2 * ks + bbit));
#pragma unroll
            for (int ni = 0; ni < 8; ++ni)
#pragma unroll
                for (int mi = 0; mi < 4; ++mi)
                    mma16(acc[mi][ni], a[mi][0], a[mi][1], a[mi][2], a[mi][3],
                          b[ni][0], b[ni][1]);
        }
    }

    // Epilogue: c-frag rows (g, g+8), cols (2t4, 2t4+1)
#pragma unroll
    for (int mi = 0; mi < 4; ++mi) {
        const int r_lo = row0 + wm * 64 + mi * 16 + g;
#pragma unroll
        for (int ni = 0; ni < 8; ++ni) {
            const int c = col0 + wn * 64 + ni * 8 + t4 * 2;
            const float v00 = acc[mi][ni][0] + bias[c];
            const float v01 = acc[mi][ni][1] + bias[c + 1];
            const float v10 = acc[mi][ni][2] + bias[c];
            const float v11 = acc[mi][ni][3] + bias[c + 1];
            if (MODE == 0) {
                const int which = c >> 10;
                const int rem = c & 1023;
                const int hh = rem >> 6;
                const int dl = rem & 63;  // even, pair inside head
                const int bb0 = r_lo >> 11, t0 = r_lo & 2047;
                const int bb1 = (r_lo + 8) >> 11, t1 = (r_lo + 8) & 2047;
                __half* dst = (which == 0) ? g_q : (which == 1 ? g_k : g_v);
                const float sc = (which == 0) ? 0.125f : 1.0f;
                *(__half2*)(dst + ((size_t)(bb0 * HH + hh) * TT + t0) * HD + dl) =
                    __floats2half2_rn(v00 * sc, v01 * sc);
                *(__half2*)(dst + ((size_t)(bb1 * HH + hh) * TT + t1) * HD + dl) =
                    __floats2half2_rn(v10 * sc, v11 * sc);
            } else {
                float2 lo, hi;
                lo.x = v00; lo.y = v01;
                hi.x = v10; hi.y = v11;
                *(float2*)(out + (size_t)r_lo * NW + c) = lo;
                *(float2*)(out + (size_t)(r_lo + 8) * NW + c) = hi;
            }
        }
    }
}

// ---------------------------------------------------------------------------
// Flash attention (causal), fp16 mma + ldmatrix, 3-stage cp.async K/V ring,
// one __syncthreads per kv tile. One block = 128 q rows of one (b,h).
// smem: Q 16384 + 3 x (K 8192 + V 8192) = 65536 B  (swizzled 128B rows)
// ---------------------------------------------------------------------------
__global__ __launch_bounds__(256, 2) void attn_mma()
{
    extern __shared__ __align__(16) char smc[];
    const uint32_t sb = s2u(smc);
    const uint32_t sQ = sb;

    const int tid = threadIdx.x;
    const int lane = tid & 31;
    const int w = tid >> 5;
    const int g = lane >> 2, t4 = lane & 3;
    const int qt = 15 - (int)blockIdx.x;  // heavy tiles first
    const int h = blockIdx.y, b = blockIdx.z;

    const size_t ho = (size_t)(b * HH + h) * TT * HD;
    const __half* qb = g_q + ho;
    const __half* kb = g_k + ho;
    const __half* vb = g_v + ho;

    auto issueKV = [&](int kt, int st) {
        const uint32_t base = sb + 16384 + st * 16384;
#pragma unroll
        for (int r = 0; r < 2; ++r) {
            const int idx = tid + r * 256;
            const int m = idx >> 3, c = idx & 7;
            const uint32_t o = swz(m, c);
            cpa16(base + o, kb + (size_t)(kt * 64 + m) * HD + c * 8);
            cpa16(base + 8192 + o, vb + (size_t)(kt * 64 + m) * HD + c * 8);
        }
        cp_commit();
    };

    // Q tile + first KV in group 0
#pragma unroll
    for (int r = 0; r < 4; ++r) {
        const int idx = tid + r * 256;
        const int m = idx >> 3, c = idx & 7;
        cpa16(sQ + swz(m, c), qb + (size_t)(qt * 128 + m) * HD + c * 8);
    }
    issueKV(0, 0);

    const int nkt = 2 * qt + 2;
    if (nkt > 1) issueKV(1, 1);

    float O[8][4];
#pragma unroll
    for (int n = 0; n < 8; ++n)
#pragma unroll
        for (int j = 0; j < 4; ++j) O[n][j] = 0.0f;
    float m_lo = -1e30f, m_hi = -1e30f, l_lo = 0.0f, l_hi = 0.0f;

    const int rlo = qt * 128 + w * 16 + g;

    // ldmatrix lane row/chunk decomposition
    const int qr = w * 16 + (lane & 15);
    const int qbit = lane >> 4;
    const int kr = (lane & 7) + ((lane >> 4) << 3);  // + np*16
    const int kbit = (lane >> 3) & 1;
    const int vr = lane & 15;                        // + 16*s
    const int vbit = (lane >> 4) & 1;

    uint32_t aq[4][4];  // Q fragments, hoisted

    for (int kt = 0; kt < nkt; ++kt) {
        if (kt + 1 < nkt) cp_wait<1>(); else cp_wait<0>();
        __syncthreads();
        if (kt + 2 < nkt) issueKV(kt + 2, (kt + 2) % 3);
        if (kt == 0) {
#pragma unroll
            for (int s = 0; s < 4; ++s)
                ldm4(aq[s][0], aq[s][1], aq[s][2], aq[s][3],
                     sQ + swz(qr, 2 * s + qbit));
        }
        const uint32_t Ks = sb + 16384 + (kt % 3) * 16384;
        const uint32_t Vs = Ks + 8192;

        // S = Q K^T  (warp: 16 rows x 64 kv cols)
        float Sa[8][4];
#pragma unroll
        for (int n = 0; n < 8; ++n)
#pragma unroll
            for (int j = 0; j < 4; ++j) Sa[n][j] = 0.0f;

#pragma unroll
        for (int s = 0; s < 4; ++s) {
            uint32_t bk[8][2];
#pragma unroll
            for (int np = 0; np < 4; ++np) {
                const int r = kr + np * 16;
                ldm4(bk[2 * np][0], bk[2 * np][1], bk[2 * np + 1][0], bk[2 * np + 1][1],
                     Ks + swz(r, 2 * s + kbit));
            }
#pragma unroll
            for (int n = 0; n < 8; ++n)
                mma16(Sa[n], aq[s][0], aq[s][1], aq[s][2], aq[s][3],
                      bk[n][0], bk[n][1]);
        }

        // causal mask (only the last two kv tiles cross the diagonal)
        if (kt >= 2 * qt) {
#pragma unroll
            for (int n = 0; n < 8; ++n) {
                const int c = kt * 64 + n * 8 + t4 * 2;
                if (c > rlo) Sa[n][0] = -1e30f;
                if (c + 1 > rlo) Sa[n][1] = -1e30f;
                if (c > rlo + 8) Sa[n][2] = -1e30f;
                if (c + 1 > rlo + 8) Sa[n][3] = -1e30f;
            }
        }

        // online softmax (rows g, g+8; quad reduction)
        float mx_lo = -1e30f, mx_hi = -1e30f;
#pragma unroll
        for (int n = 0; n < 8; ++n) {
            mx_lo = fmaxf(mx_lo, fmaxf(Sa[n][0], Sa[n][1]));
            mx_hi = fmaxf(mx_hi, fmaxf(Sa[n][2], Sa[n][3]));
        }
        mx_lo = fmaxf(mx_lo, __shfl_xor_sync(0xffffffffu, mx_lo, 1));
        mx_lo = fmaxf(mx_lo, __shfl_xor_sync(0xffffffffu, mx_lo, 2));
        mx_hi = fmaxf(mx_hi, __shfl_xor_sync(0xffffffffu, mx_hi, 1));
        mx_hi = fmaxf(mx_hi, __shfl_xor_sync(0xffffffffu, mx_hi, 2));
        const float mn_lo = fmaxf(m_lo, mx_lo);
        const float mn_hi = fmaxf(m_hi, mx_hi);
        const float al_lo = __expf(m_lo - mn_lo);
        const float al_hi = __expf(m_hi - mn_hi);
        m_lo = mn_lo;
        m_hi = mn_hi;
        float rs_lo = 0.0f, rs_hi = 0.0f;
#pragma unroll
        for (int n = 0; n < 8; ++n) {
            Sa[n][0] = __expf(Sa[n][0] - mn_lo);
            Sa[n][1] = __expf(Sa[n][1] - mn_lo);
            Sa[n][2] = __expf(Sa[n][2] - mn_hi);
            Sa[n][3] = __expf(Sa[n][3] - mn_hi);
            rs_lo += Sa[n][0] + Sa[n][1];
            rs_hi += Sa[n][2] + Sa[n][3];
        }
        rs_lo += __shfl_xor_sync(0xffffffffu, rs_lo, 1);
        rs_lo += __shfl_xor_sync(0xffffffffu, rs_lo, 2);
        rs_hi += __shfl_xor_sync(0xffffffffu, rs_hi, 1);
        rs_hi += __shfl_xor_sync(0xffffffffu, rs_hi, 2);
        l_lo = l_lo * al_lo + rs_lo;
        l_hi = l_hi * al_hi + rs_hi;
#pragma unroll
        for (int n = 0; n < 8; ++n) {
            O[n][0] *= al_lo;
            O[n][1] *= al_lo;
            O[n][2] *= al_hi;
            O[n][3] *= al_hi;
        }

        // O += P V : P a-frags directly from S c-frag pairs (fp16 pack)
#pragma unroll
        for (int s = 0; s < 4; ++s) {
            const uint32_t pa0 = packh2(Sa[2 * s][0], Sa[2 * s][1]);
            const uint32_t pa1 = packh2(Sa[2 * s][2], Sa[2 * s][3]);
            const uint32_t pa2 = packh2(Sa[2 * s + 1][0], Sa[2 * s + 1][1]);
            const uint32_t pa3 = packh2(Sa[2 * s + 1][2], Sa[2 * s + 1][3]);
            uint32_t bv[8][2];
#pragma unroll
            for (int vp = 0; vp < 4; ++vp) {
                const int r = 16 * s + vr;
                ldm4t(bv[2 * vp][0], bv[2 * vp][1], bv[2 * vp + 1][0], bv[2 * vp + 1][1],
                      Vs + swz(r, 2 * vp + vbit));
            }
#pragma unroll
            for (int n = 0; n < 8; ++n)
                mma16(O[n], pa0, pa1, pa2, pa3, bv[n][0], bv[n][1]);
        }
    }

    // write y [B,T,C] half
    const float inv_lo = 1.0f / l_lo;
    const float inv_hi = 1.0f / l_hi;
    __half* y0 = g_y + (size_t)(b * TT + rlo) * CC;
    __half* y1 = g_y + (size_t)(b * TT + rlo + 8) * CC;
#pragma unroll
    for (int n = 0; n < 8; ++n) {
        const int c = h * HD + n * 8 + t4 * 2;
        *(__half2*)(y0 + c) = __floats2half2_rn(O[n][0] * inv_lo, O[n][1] * inv_lo);
        *(__half2*)(y1 + c) = __floats2half2_rn(O[n][2] * inv_hi, O[n][3] * inv_hi);
    }
}

// ---------------------------------------------------------------------------
extern "C" void kernel_launch(void* const* d_in, const int* in_sizes, int n_in,
                              void* d_out, int out_size)
{
    (void)in_sizes; (void)n_in; (void)out_size;
    const float* x      = (const float*)d_in[0];
    const float* W_attn = (const float*)d_in[1];
    const float* b_attn = (const float*)d_in[2];
    const float* W_proj = (const float*)d_in[3];
    const float* b_proj = (const float*)d_in[4];
    float* out = (float*)d_out;

    const int smem_gemm = 3 * 49152;          // 147456 B
    const int smem_attn = 16384 + 3 * 16384;  // 65536 B
    cudaFuncSetAttribute(gemm_mma<0, 3072>,
                         cudaFuncAttributeMaxDynamicSharedMemorySize, smem_gemm);
    cudaFuncSetAttribute(gemm_mma<1, 1024>,
                         cudaFuncAttributeMaxDynamicSharedMemorySize, smem_gemm);
    cudaFuncSetAttribute(attn_mma,
                         cudaFuncAttributeMaxDynamicSharedMemorySize, smem_attn);

    // 0) convert inputs to half (+ transpose W)
    prep_x<<<(BB * TT * CC / 4) / 256, 256>>>(x);
    prep_w<<<dim3(3072 / 32, 1024 / 32), dim3(32, 8)>>>(W_attn, 3072, 0);
    prep_w<<<dim3(1024 / 32, 1024 / 32), dim3(32, 8)>>>(W_proj, 1024, 1);

    // 1) QKV GEMM + bias -> q/k/v (half)   BM=128 BN=256
    gemm_mma<0, 3072><<<dim3(12, 32), 256, smem_gemm>>>(b_attn, nullptr);

    // 2) causal flash attention -> g_y (half)
    attn_mma<<<dim3(16, HH, BB), 256, smem_attn>>>();

    // 3) output projection + bias -> out (f32)  (128 blocks: single wave)
    gemm_mma<1, 1024><<<dim3(4, 32), 256, smem_gemm>>>(b_proj, out);
}

// round 13
// speedup vs baseline: 1.5711x; 1.5711x over previous
#include <cuda_runtime.h>
#include <cuda_fp16.h>
#include <cstdint>

// Problem constants
#define BB 2
#define TT 2048
#define CC 1024
#define HH 16
#define HD 64

// Scratch (no cudaMalloc). All fp16 where consumed by mma.
__device__ __align__(256) __half g_q[BB * HH * TT * HD];
__device__ __align__(256) __half g_k[BB * HH * TT * HD];
__device__ __align__(256) __half g_v[BB * HH * TT * HD];
__device__ __align__(256) __half g_y[BB * TT * CC];
__device__ __align__(256) __half g_xr[BB * TT * CC];
__device__ __align__(256) __half g_war[3 * CC * CC];
__device__ __align__(256) __half g_wpr[CC * CC];

// ---------------------------------------------------------------------------
// helpers
// ---------------------------------------------------------------------------
__device__ __forceinline__ uint32_t packh2(float lo, float hi) {
    __half2 h = __floats2half2_rn(lo, hi);
    return *reinterpret_cast<uint32_t*>(&h);
}

__device__ __forceinline__ void mma16(float* c, uint32_t a0, uint32_t a1,
                                      uint32_t a2, uint32_t a3,
                                      uint32_t b0, uint32_t b1) {
    asm volatile(
        "mma.sync.aligned.m16n8k16.row.col.f32.f16.f16.f32 "
        "{%0,%1,%2,%3}, {%4,%5,%6,%7}, {%8,%9}, {%0,%1,%2,%3};"
        : "+f"(c[0]), "+f"(c[1]), "+f"(c[2]), "+f"(c[3])
        : "r"(a0), "r"(a1), "r"(a2), "r"(a3), "r"(b0), "r"(b1));
}

__device__ __forceinline__ void ldm4(uint32_t& r0, uint32_t& r1, uint32_t& r2,
                                     uint32_t& r3, uint32_t a) {
    asm volatile("ldmatrix.sync.aligned.m8n8.x4.shared.b16 {%0,%1,%2,%3}, [%4];"
                 : "=r"(r0), "=r"(r1), "=r"(r2), "=r"(r3) : "r"(a));
}
__device__ __forceinline__ void ldm4t(uint32_t& r0, uint32_t& r1, uint32_t& r2,
                                      uint32_t& r3, uint32_t a) {
    asm volatile("ldmatrix.sync.aligned.m8n8.x4.trans.shared.b16 {%0,%1,%2,%3}, [%4];"
                 : "=r"(r0), "=r"(r1), "=r"(r2), "=r"(r3) : "r"(a));
}

__device__ __forceinline__ void cpa16(uint32_t dst, const void* src) {
    asm volatile("cp.async.cg.shared.global [%0], [%1], 16;" :: "r"(dst), "l"(src));
}
__device__ __forceinline__ void cp_commit() {
    asm volatile("cp.async.commit_group;");
}
template <int N>
__device__ __forceinline__ void cp_wait() {
    asm volatile("cp.async.wait_group %0;" :: "n"(N));
}

__device__ __forceinline__ uint32_t s2u(const void* p) {
    return (uint32_t)__cvta_generic_to_shared(p);
}

// XOR swizzle: 128B rows of 8 x 16B chunks; chunk c of row m lives at c^(m&7)
__device__ __forceinline__ uint32_t swz(int m, int c) {
    return (uint32_t)(m * 128 + ((c ^ (m & 7)) << 4));
}

// ---------------------------------------------------------------------------
// prep kernels
// ---------------------------------------------------------------------------
__global__ void prep_x(const float* __restrict__ x) {
    const int i = blockIdx.x * blockDim.x + threadIdx.x;
    const float4 v = *(const float4*)(x + i * 4);
    __half2* p = (__half2*)(g_xr + i * 4);
    p[0] = __floats2half2_rn(v.x, v.y);
    p[1] = __floats2half2_rn(v.z, v.w);
}

// W [1024 x Nc] row-major f32 -> Wt [Nc x 1024] half
__global__ void prep_w(const float* __restrict__ W, int Nc, int which) {
    __shared__ float t[32][33];
    __half* Wt = which ? g_wpr : g_war;
    const int n0 = blockIdx.x * 32, k0 = blockIdx.y * 32;
    const int tx = threadIdx.x, ty0 = threadIdx.y;
#pragma unroll
    for (int i = 0; i < 4; ++i) {
        const int ty = ty0 + i * 8;
        t[ty][tx] = W[(size_t)(k0 + ty) * Nc + n0 + tx];
    }
    __syncthreads();
#pragma unroll
    for (int i = 0; i < 4; ++i) {
        const int ty = ty0 + i * 8;
        Wt[(size_t)(n0 + ty) * 1024 + k0 + tx] = __float2half(t[tx][ty]);
    }
}

// ---------------------------------------------------------------------------
// GEMM (round-9 proven config): C[M,N] = A[M,1024] @ W[1024,N] + bias
//   MODE 0: A=g_xr, Wt=g_war, scatter half q/k/v (q scaled 0.125)
//   MODE 1: A=g_y,  Wt=g_wpr, out full fp32
// BM=BN=128, BK=64, 256 threads (8 warps 4m x 2n, warp tile 32x64)
// 3-stage cp.async ring, ONE __syncthreads per k-tile, swizzled 128B rows.
// smem: 3 stages x (A 16384 + B 16384) = 98304 B.  2 CTAs/SM, 128 regs.
// ---------------------------------------------------------------------------
template <int MODE, int NW>
__global__ __launch_bounds__(256, 2) void gemm_mma(const float* __restrict__ bias,
                                                   float* __restrict__ out)
{
    extern __shared__ __align__(16) char smem[];
    const uint32_t sb = s2u(smem);

    const __half* A  = (MODE == 0) ? g_xr : g_y;
    const __half* Wt = (MODE == 0) ? g_war : g_wpr;

    const int tid = threadIdx.x;
    const int lane = tid & 31;
    const int g = lane >> 2, t4 = lane & 3;
    const int w = tid >> 5;
    const int wm = w & 3, wn = w >> 2;
    const int row0 = blockIdx.y * 128, col0 = blockIdx.x * 128;

    auto issue = [&](int kt, int st) {
        const uint32_t base = sb + st * 32768;
#pragma unroll
        for (int r = 0; r < 4; ++r) {
            const int idx = tid + r * 256;
            const int m = idx >> 3, c = idx & 7;
            const uint32_t o = swz(m, c);
            cpa16(base + o, A + (size_t)(row0 + m) * 1024 + kt * 64 + c * 8);
            cpa16(base + 16384 + o, Wt + (size_t)(col0 + m) * 1024 + kt * 64 + c * 8);
        }
        cp_commit();
    };

    float acc[2][8][4];
#pragma unroll
    for (int mi = 0; mi < 2; ++mi)
#pragma unroll
        for (int ni = 0; ni < 8; ++ni)
#pragma unroll
            for (int j = 0; j < 4; ++j) acc[mi][ni][j] = 0.0f;

    // ldmatrix lane row/chunk decomposition
    const int ar = wm * 32 + (lane & 15);                      // + mi*16
    const int abit = lane >> 4;                                // chunk low bit
    const int br = wn * 64 + (lane & 7) + ((lane >> 4) << 3);  // + np*16
    const int bbit = (lane >> 3) & 1;

    issue(0, 0);
    issue(1, 1);
    for (int kt = 0; kt < 16; ++kt) {
        if (kt + 1 < 16) cp_wait<1>(); else cp_wait<0>();
        __syncthreads();
        if (kt + 2 < 16) issue(kt + 2, (kt + 2) % 3);
        const uint32_t a_s = sb + (kt % 3) * 32768;
        const uint32_t b_s = a_s + 16384;
#pragma unroll
        for (int ks = 0; ks < 4; ++ks) {
            uint32_t a[2][4];
#pragma unroll
            for (int mi = 0; mi < 2; ++mi) {
                const int r = ar + mi * 16;
                ldm4(a[mi][0], a[mi][1], a[mi][2], a[mi][3],
                     a_s + swz(r, 2 * ks + abit));
            }
            uint32_t b[8][2];
#pragma unroll
            for (int np = 0; np < 4; ++np) {
                const int r = br + np * 16;
                ldm4(b[2 * np][0], b[2 * np][1], b[2 * np + 1][0], b[2 * np + 1][1],
                     b_s + swz(r, 2 * ks + bbit));
            }
#pragma unroll
            for (int ni = 0; ni < 8; ++ni) {
                mma16(acc[0][ni], a[0][0], a[0][1], a[0][2], a[0][3], b[ni][0], b[ni][1]);
                mma16(acc[1][ni], a[1][0], a[1][1], a[1][2], a[1][3], b[ni][0], b[ni][1]);
            }
        }
    }

    // Epilogue: c-frag rows (g, g+8), cols (2t4, 2t4+1)
#pragma unroll
    for (int mi = 0; mi < 2; ++mi) {
        const int r_lo = row0 + wm * 32 + mi * 16 + g;
#pragma unroll
        for (int ni = 0; ni < 8; ++ni) {
            const int c = col0 + wn * 64 + ni * 8 + t4 * 2;
            const float v00 = acc[mi][ni][0] + bias[c];
            const float v01 = acc[mi][ni][1] + bias[c + 1];
            const float v10 = acc[mi][ni][2] + bias[c];
            const float v11 = acc[mi][ni][3] + bias[c + 1];
            if (MODE == 0) {
                const int which = c >> 10;
                const int rem = c & 1023;
                const int hh = rem >> 6;
                const int dl = rem & 63;  // even, pair inside head
                const int bb0 = r_lo >> 11, t0 = r_lo & 2047;
                const int bb1 = (r_lo + 8) >> 11, t1 = (r_lo + 8) & 2047;
                __half* dst = (which == 0) ? g_q : (which == 1 ? g_k : g_v);
                const float sc = (which == 0) ? 0.125f : 1.0f;
                *(__half2*)(dst + ((size_t)(bb0 * HH + hh) * TT + t0) * HD + dl) =
                    __floats2half2_rn(v00 * sc, v01 * sc);
                *(__half2*)(dst + ((size_t)(bb1 * HH + hh) * TT + t1) * HD + dl) =
                    __floats2half2_rn(v10 * sc, v11 * sc);
            } else {
                float2 lo, hi;
                lo.x = v00; lo.y = v01;
                hi.x = v10; hi.y = v11;
                *(float2*)(out + (size_t)r_lo * NW + c) = lo;
                *(float2*)(out + (size_t)(r_lo + 8) * NW + c) = hi;
            }
        }
    }
}

// ---------------------------------------------------------------------------
// Flash attention (causal), fp16 mma + ldmatrix.
// 3-STAGE ring of 128-row K/V pair stages (stage = K 16KB + V 16KB = 32KB);
// two 64-row kv halves computed per barrier. Q (16KB) ALIASES the K half of
// stage 2: Q fragments are hoisted into registers at pr==0 (with one extra
// barrier) before stage 2 is first written by the pair-2 prefetch.
// One block = 128 q rows of one (b,h); 8 warps m-split (warp-local softmax).
// smem: 3 x 32768 = 98304 B.  2 CTAs/SM.
// ---------------------------------------------------------------------------
__global__ __launch_bounds__(256, 2) void attn_mma()
{
    extern __shared__ __align__(16) char smc[];
    const uint32_t sb = s2u(smc);
    const uint32_t sQ = sb + 65536;  // aliases stage-2 K half

    const int tid = threadIdx.x;
    const int lane = tid & 31;
    const int w = tid >> 5;
    const int g = lane >> 2, t4 = lane & 3;
    const int qt = 15 - (int)blockIdx.x;  // heavy tiles first
    const int h = blockIdx.y, b = blockIdx.z;

    const size_t ho = (size_t)(b * HH + h) * TT * HD;
    const __half* qb = g_q + ho;
    const __half* kb = g_k + ho;
    const __half* vb = g_v + ho;

    // stage = 128 K rows (16 KB) + 128 V rows (16 KB)
    auto issueKV = [&](int pr, int st) {
        const uint32_t base = sb + st * 32768;
#pragma unroll
        for (int r = 0; r < 4; ++r) {
            const int idx = tid + r * 256;
            const int m = idx >> 3, c = idx & 7;
            const uint32_t o = swz(m, c);
            cpa16(base + o, kb + (size_t)(pr * 128 + m) * HD + c * 8);
            cpa16(base + 16384 + o, vb + (size_t)(pr * 128 + m) * HD + c * 8);
        }
        cp_commit();
    };

    // Q tile into sQ, committed together with KV pair 0 (group 0)
#pragma unroll
    for (int r = 0; r < 4; ++r) {
        const int idx = tid + r * 256;
        const int m = idx >> 3, c = idx & 7;
        cpa16(sQ + swz(m, c), qb + (size_t)(qt * 128 + m) * HD + c * 8);
    }
    issueKV(0, 0);

    const int npairs = qt + 1;
    if (npairs > 1) issueKV(1, 1);

    float O[8][4];
#pragma unroll
    for (int n = 0; n < 8; ++n)
#pragma unroll
        for (int j = 0; j < 4; ++j) O[n][j] = 0.0f;
    float m_lo = -1e30f, m_hi = -1e30f, l_lo = 0.0f, l_hi = 0.0f;

    const int rlo = qt * 128 + w * 16 + g;

    // ldmatrix lane row/chunk decomposition
    const int qr = w * 16 + (lane & 15);
    const int qbit = lane >> 4;
    const int kr = (lane & 7) + ((lane >> 4) << 3);  // + np*16
    const int kbit = (lane >> 3) & 1;
    const int vr = lane & 15;                        // + 16*s
    const int vbit = (lane >> 4) & 1;

    uint32_t aq[4][4];  // Q fragments, hoisted

    for (int pr = 0; pr < npairs; ++pr) {
        if (pr + 1 < npairs) cp_wait<1>(); else cp_wait<0>();
        __syncthreads();
        if (pr == 0) {
            // Hoist Q fragments BEFORE stage-2 prefetch overwrites sQ.
#pragma unroll
            for (int s = 0; s < 4; ++s)
                ldm4(aq[s][0], aq[s][1], aq[s][2], aq[s][3],
                     sQ + swz(qr, 2 * s + qbit));
            if (npairs > 2) __syncthreads();  // all Q reads done before alias write
        }
        if (pr + 2 < npairs) issueKV(pr + 2, (pr + 2) % 3);
        const uint32_t stbase = sb + (pr % 3) * 32768;

#pragma unroll
        for (int half = 0; half < 2; ++half) {
            const int kt = 2 * pr + half;
            const uint32_t Ks = stbase + half * 8192;          // rows 64*half..
            const uint32_t Vs = stbase + 16384 + half * 8192;

            // S = Q K^T  (warp: 16 rows x 64 kv cols)
            float Sa[8][4];
#pragma unroll
            for (int n = 0; n < 8; ++n)
#pragma unroll
                for (int j = 0; j < 4; ++j) Sa[n][j] = 0.0f;

#pragma unroll
            for (int s = 0; s < 4; ++s) {
                uint32_t bk[8][2];
#pragma unroll
                for (int np = 0; np < 4; ++np) {
                    const int r = kr + np * 16;
                    ldm4(bk[2 * np][0], bk[2 * np][1], bk[2 * np + 1][0],
                         bk[2 * np + 1][1], Ks + swz(r, 2 * s + kbit));
                }
#pragma unroll
                for (int n = 0; n < 8; ++n)
                    mma16(Sa[n], aq[s][0], aq[s][1], aq[s][2], aq[s][3],
                          bk[n][0], bk[n][1]);
            }

            // causal mask (only the last two kv tiles cross the diagonal)
            if (kt >= 2 * qt) {
#pragma unroll
                for (int n = 0; n < 8; ++n) {
                    const int c = kt * 64 + n * 8 + t4 * 2;
                    if (c > rlo) Sa[n][0] = -1e30f;
                    if (c + 1 > rlo) Sa[n][1] = -1e30f;
                    if (c > rlo + 8) Sa[n][2] = -1e30f;
                    if (c + 1 > rlo + 8) Sa[n][3] = -1e30f;
                }
            }

            // online softmax (rows g, g+8; quad reduction)
            float mx_lo = -1e30f, mx_hi = -1e30f;
#pragma unroll
            for (int n = 0; n < 8; ++n) {
                mx_lo = fmaxf(mx_lo, fmaxf(Sa[n][0], Sa[n][1]));
                mx_hi = fmaxf(mx_hi, fmaxf(Sa[n][2], Sa[n][3]));
            }
            mx_lo = fmaxf(mx_lo, __shfl_xor_sync(0xffffffffu, mx_lo, 1));
            mx_lo = fmaxf(mx_lo, __shfl_xor_sync(0xffffffffu, mx_lo, 2));
            mx_hi = fmaxf(mx_hi, __shfl_xor_sync(0xffffffffu, mx_hi, 1));
            mx_hi = fmaxf(mx_hi, __shfl_xor_sync(0xffffffffu, mx_hi, 2));
            const float mn_lo = fmaxf(m_lo, mx_lo);
            const float mn_hi = fmaxf(m_hi, mx_hi);
            const float al_lo = __expf(m_lo - mn_lo);
            const float al_hi = __expf(m_hi - mn_hi);
            m_lo = mn_lo;
            m_hi = mn_hi;
            float rs_lo = 0.0f, rs_hi = 0.0f;
#pragma unroll
            for (int n = 0; n < 8; ++n) {
                Sa[n][0] = __expf(Sa[n][0] - mn_lo);
                Sa[n][1] = __expf(Sa[n][1] - mn_lo);
                Sa[n][2] = __expf(Sa[n][2] - mn_hi);
                Sa[n][3] = __expf(Sa[n][3] - mn_hi);
                rs_lo += Sa[n][0] + Sa[n][1];
                rs_hi += Sa[n][2] + Sa[n][3];
            }
            rs_lo += __shfl_xor_sync(0xffffffffu, rs_lo, 1);
            rs_lo += __shfl_xor_sync(0xffffffffu, rs_lo, 2);
            rs_hi += __shfl_xor_sync(0xffffffffu, rs_hi, 1);
            rs_hi += __shfl_xor_sync(0xffffffffu, rs_hi, 2);
            l_lo = l_lo * al_lo + rs_lo;
            l_hi = l_hi * al_hi + rs_hi;
#pragma unroll
            for (int n = 0; n < 8; ++n) {
                O[n][0] *= al_lo;
                O[n][1] *= al_lo;
                O[n][2] *= al_hi;
                O[n][3] *= al_hi;
            }

            // O += P V : P a-frags directly from S c-frag pairs (fp16 pack)
#pragma unroll
            for (int s = 0; s < 4; ++s) {
                const uint32_t pa0 = packh2(Sa[2 * s][0], Sa[2 * s][1]);
                const uint32_t pa1 = packh2(Sa[2 * s][2], Sa[2 * s][3]);
                const uint32_t pa2 = packh2(Sa[2 * s + 1][0], Sa[2 * s + 1][1]);
                const uint32_t pa3 = packh2(Sa[2 * s + 1][2], Sa[2 * s + 1][3]);
                uint32_t bv[8][2];
#pragma unroll
                for (int vp = 0; vp < 4; ++vp) {
                    const int r = 16 * s + vr;
                    ldm4t(bv[2 * vp][0], bv[2 * vp][1], bv[2 * vp + 1][0],
                          bv[2 * vp + 1][1], Vs + swz(r, 2 * vp + vbit));
                }
#pragma unroll
                for (int n = 0; n < 8; ++n)
                    mma16(O[n], pa0, pa1, pa2, pa3, bv[n][0], bv[n][1]);
            }
        }
    }

    // write y [B,T,C] half
    const float inv_lo = 1.0f / l_lo;
    const float inv_hi = 1.0f / l_hi;
    __half* y0 = g_y + (size_t)(b * TT + rlo) * CC;
    __half* y1 = g_y + (size_t)(b * TT + rlo + 8) * CC;
#pragma unroll
    for (int n = 0; n < 8; ++n) {
        const int c = h * HD + n * 8 + t4 * 2;
        *(__half2*)(y0 + c) = __floats2half2_rn(O[n][0] * inv_lo, O[n][1] * inv_lo);
        *(__half2*)(y1 + c) = __floats2half2_rn(O[n][2] * inv_hi, O[n][3] * inv_hi);
    }
}

// ---------------------------------------------------------------------------
extern "C" void kernel_launch(void* const* d_in, const int* in_sizes, int n_in,
                              void* d_out, int out_size)
{
    (void)in_sizes; (void)n_in; (void)out_size;
    const float* x      = (const float*)d_in[0];
    const float* W_attn = (const float*)d_in[1];
    const float* b_attn = (const float*)d_in[2];
    const float* W_proj = (const float*)d_in[3];
    const float* b_proj = (const float*)d_in[4];
    float* out = (float*)d_out;

    const int smem_gemm = 3 * 32768;  // 98304 B
    const int smem_attn = 3 * 32768;  // 98304 B (Q aliases stage 2)
    cudaFuncSetAttribute(gemm_mma<0, 3072>,
                         cudaFuncAttributeMaxDynamicSharedMemorySize, smem_gemm);
    cudaFuncSetAttribute(gemm_mma<1, 1024>,
                         cudaFuncAttributeMaxDynamicSharedMemorySize, smem_gemm);
    cudaFuncSetAttribute(attn_mma,
                         cudaFuncAttributeMaxDynamicSharedMemorySize, smem_attn);

    // 0) convert inputs to half (+ transpose W)
    prep_x<<<(BB * TT * CC / 4) / 256, 256>>>(x);
    prep_w<<<dim3(3072 / 32, 1024 / 32), dim3(32, 8)>>>(W_attn, 3072, 0);
    prep_w<<<dim3(1024 / 32, 1024 / 32), dim3(32, 8)>>>(W_proj, 1024, 1);

    // 1) QKV GEMM + bias -> q/k/v (half)
    gemm_mma<0, 3072><<<dim3(24, 32), 256, smem_gemm>>>(b_attn, nullptr);

    // 2) causal flash attention -> g_y (half)
    attn_mma<<<dim3(16, HH, BB), 256, smem_attn>>>();

    // 3) output projection + bias -> out (f32)
    gemm_mma<1, 1024><<<dim3(8, 32), 256, smem_gemm>>>(b_proj, out);
}

// round 17
// speedup vs baseline: 1.6063x; 1.0224x over previous
#include <cuda_runtime.h>
#include <cuda_fp16.h>
#include <cstdint>

// Problem constants
#define BB 2
#define TT 2048
#define CC 1024
#define HH 16
#define HD 64

// Scratch (no cudaMalloc). All fp16 where consumed by mma.
__device__ __align__(256) __half g_q[BB * HH * TT * HD];
__device__ __align__(256) __half g_k[BB * HH * TT * HD];
__device__ __align__(256) __half g_v[BB * HH * TT * HD];
__device__ __align__(256) __half g_y[BB * TT * CC];
__device__ __align__(256) __half g_xr[BB * TT * CC];
__device__ __align__(256) __half g_war[3 * CC * CC];
__device__ __align__(256) __half g_wpr[CC * CC];

// ---------------------------------------------------------------------------
// helpers
// ---------------------------------------------------------------------------
__device__ __forceinline__ uint32_t packh2(float lo, float hi) {
    __half2 h = __floats2half2_rn(lo, hi);
    return *reinterpret_cast<uint32_t*>(&h);
}

__device__ __forceinline__ float ex2f(float x) {
    float y;
    asm("ex2.approx.ftz.f32 %0, %1;" : "=f"(y) : "f"(x));
    return y;
}

__device__ __forceinline__ void mma16(float* c, uint32_t a0, uint32_t a1,
                                      uint32_t a2, uint32_t a3,
                                      uint32_t b0, uint32_t b1) {
    asm volatile(
        "mma.sync.aligned.m16n8k16.row.col.f32.f16.f16.f32 "
        "{%0,%1,%2,%3}, {%4,%5,%6,%7}, {%8,%9}, {%0,%1,%2,%3};"
        : "+f"(c[0]), "+f"(c[1]), "+f"(c[2]), "+f"(c[3])
        : "r"(a0), "r"(a1), "r"(a2), "r"(a3), "r"(b0), "r"(b1));
}

__device__ __forceinline__ void ldm4(uint32_t& r0, uint32_t& r1, uint32_t& r2,
                                     uint32_t& r3, uint32_t a) {
    asm volatile("ldmatrix.sync.aligned.m8n8.x4.shared.b16 {%0,%1,%2,%3}, [%4];"
                 : "=r"(r0), "=r"(r1), "=r"(r2), "=r"(r3) : "r"(a));
}
__device__ __forceinline__ void ldm4t(uint32_t& r0, uint32_t& r1, uint32_t& r2,
                                      uint32_t& r3, uint32_t a) {
    asm volatile("ldmatrix.sync.aligned.m8n8.x4.trans.shared.b16 {%0,%1,%2,%3}, [%4];"
                 : "=r"(r0), "=r"(r1), "=r"(r2), "=r"(r3) : "r"(a));
}

__device__ __forceinline__ void cpa16(uint32_t dst, const void* src) {
    asm volatile("cp.async.cg.shared.global [%0], [%1], 16;" :: "r"(dst), "l"(src));
}
__device__ __forceinline__ void cp_commit() {
    asm volatile("cp.async.commit_group;");
}
template <int N>
__device__ __forceinline__ void cp_wait() {
    asm volatile("cp.async.wait_group %0;" :: "n"(N));
}

__device__ __forceinline__ uint32_t s2u(const void* p) {
    return (uint32_t)__cvta_generic_to_shared(p);
}

// XOR swizzle: 128B rows of 8 x 16B chunks; chunk c of row m lives at c^(m&7)
__device__ __forceinline__ uint32_t swz(int m, int c) {
    return (uint32_t)(m * 128 + ((c ^ (m & 7)) << 4));
}

// ---------------------------------------------------------------------------
// prep kernels
// ---------------------------------------------------------------------------
__global__ void prep_x(const float* __restrict__ x) {
    const int i = blockIdx.x * blockDim.x + threadIdx.x;
    const float4 v = *(const float4*)(x + i * 4);
    __half2* p = (__half2*)(g_xr + i * 4);
    p[0] = __floats2half2_rn(v.x, v.y);
    p[1] = __floats2half2_rn(v.z, v.w);
}

// W [1024 x Nc] row-major f32 -> Wt [Nc x 1024] half
__global__ void prep_w(const float* __restrict__ W, int Nc, int which) {
    __shared__ float t[32][33];
    __half* Wt = which ? g_wpr : g_war;
    const int n0 = blockIdx.x * 32, k0 = blockIdx.y * 32;
    const int tx = threadIdx.x, ty0 = threadIdx.y;
#pragma unroll
    for (int i = 0; i < 4; ++i) {
        const int ty = ty0 + i * 8;
        t[ty][tx] = W[(size_t)(k0 + ty) * Nc + n0 + tx];
    }
    __syncthreads();
#pragma unroll
    for (int i = 0; i < 4; ++i) {
        const int ty = ty0 + i * 8;
        Wt[(size_t)(n0 + ty) * 1024 + k0 + tx] = __float2half(t[tx][ty]);
    }
}

// ---------------------------------------------------------------------------
// PERSISTENT GEMM: C[M,N] = A[M,1024] @ W[1024,N] + bias (fp16 mma, fp32 acc)
//   MODE 0: A=g_xr, Wt=g_war, scatter half q/k/v (q scaled 0.125*log2e)
//   MODE 1: A=g_y,  Wt=g_wpr, out full fp32
// BM=BN=128, BK=64, 256 threads (8 warps 4m x 2n, warp tile 32x64)
// 3-stage cp.async ring, ONE __syncthreads per k-tile. Each CTA loops over
// tiles; next tile's first two stages are issued before the epilogue so the
// scatter overlaps the refill.  smem 98304 B, 2 CTAs/SM, 128 regs.
// ---------------------------------------------------------------------------
template <int MODE, int NW, int NTILES, int NCOL>
__global__ __launch_bounds__(256, 2) void gemm_mma(const float* __restrict__ bias,
                                                   float* __restrict__ out)
{
    extern __shared__ __align__(16) char smem[];
    const uint32_t sb = s2u(smem);

    const __half* A  = (MODE == 0) ? g_xr : g_y;
    const __half* Wt = (MODE == 0) ? g_war : g_wpr;

    const int tid = threadIdx.x;
    const int lane = tid & 31;
    const int g = lane >> 2, t4 = lane & 3;
    const int w = tid >> 5;
    const int wm = w & 3, wn = w >> 2;

    // issue k-tile kt of tile t into ring stage st
    auto issue = [&](int t, int kt, int st) {
        const int r0 = (t / NCOL) * 128;
        const int c0 = (t % NCOL) * 128;
        const uint32_t base = sb + st * 32768;
#pragma unroll
        for (int r = 0; r < 4; ++r) {
            const int idx = tid + r * 256;
            const int m = idx >> 3, c = idx & 7;
            const uint32_t o = swz(m, c);
            cpa16(base + o, A + (size_t)(r0 + m) * 1024 + kt * 64 + c * 8);
            cpa16(base + 16384 + o, Wt + (size_t)(c0 + m) * 1024 + kt * 64 + c * 8);
        }
        cp_commit();
    };

    // ldmatrix lane row/chunk decomposition
    const int ar = wm * 32 + (lane & 15);                      // + mi*16
    const int abit = lane >> 4;                                // chunk low bit
    const int br = wn * 64 + (lane & 7) + ((lane >> 4) << 3);  // + np*16
    const int bbit = (lane >> 3) & 1;

    bool first = true;
    for (int tile = blockIdx.x; tile < NTILES; tile += gridDim.x) {
        const int row0 = (tile / NCOL) * 128;
        const int col0 = (tile % NCOL) * 128;

        if (first) { issue(tile, 0, 0); issue(tile, 1, 1); first = false; }

        float acc[2][8][4];
#pragma unroll
        for (int mi = 0; mi < 2; ++mi)
#pragma unroll
            for (int ni = 0; ni < 8; ++ni)
#pragma unroll
                for (int j = 0; j < 4; ++j) acc[mi][ni][j] = 0.0f;

        for (int kt = 0; kt < 16; ++kt) {
            if (kt + 1 < 16) cp_wait<1>(); else cp_wait<0>();
            __syncthreads();
            if (kt + 2 < 16) issue(tile, kt + 2, (kt + 2) % 3);
            const uint32_t a_s = sb + (kt % 3) * 32768;
            const uint32_t b_s = a_s + 16384;
#pragma unroll
            for (int ks = 0; ks < 4; ++ks) {
                uint32_t a[2][4];
#pragma unroll
                for (int mi = 0; mi < 2; ++mi) {
                    const int r = ar + mi * 16;
                    ldm4(a[mi][0], a[mi][1], a[mi][2], a[mi][3],
                         a_s + swz(r, 2 * ks + abit));
                }
                uint32_t b[8][2];
#pragma unroll
                for (int np = 0; np < 4; ++np) {
                    const int r = br + np * 16;
                    ldm4(b[2 * np][0], b[2 * np][1], b[2 * np + 1][0],
                         b[2 * np + 1][1], b_s + swz(r, 2 * ks + bbit));
                }
#pragma unroll
                for (int ni = 0; ni < 8; ++ni) {
                    mma16(acc[0][ni], a[0][0], a[0][1], a[0][2], a[0][3],
                          b[ni][0], b[ni][1]);
                    mma16(acc[1][ni], a[1][0], a[1][1], a[1][2], a[1][3],
                          b[ni][0], b[ni][1]);
                }
            }
        }

        // all stage reads for this tile done -> safe to refill for next tile
        __syncthreads();
        const int nt = tile + gridDim.x;
        if (nt < NTILES) { issue(nt, 0, 0); issue(nt, 1, 1); }

        // Epilogue (overlaps next tile's cp.async fill)
#pragma unroll
        for (int mi = 0; mi < 2; ++mi) {
            const int r_lo = row0 + wm * 32 + mi * 16 + g;
#pragma unroll
            for (int ni = 0; ni < 8; ++ni) {
                const int c = col0 + wn * 64 + ni * 8 + t4 * 2;
                const float v00 = acc[mi][ni][0] + bias[c];
                const float v01 = acc[mi][ni][1] + bias[c + 1];
                const float v10 = acc[mi][ni][2] + bias[c];
                const float v11 = acc[mi][ni][3] + bias[c + 1];
                if (MODE == 0) {
                    const int which = c >> 10;
                    const int rem = c & 1023;
                    const int hh = rem >> 6;
                    const int dl = rem & 63;  // even, pair inside head
                    const int bb0 = r_lo >> 11, t0 = r_lo & 2047;
                    const int bb1 = (r_lo + 8) >> 11, t1 = (r_lo + 8) & 2047;
                    __half* dst = (which == 0) ? g_q : (which == 1 ? g_k : g_v);
                    // q: fold softmax scale AND log2(e) (softmax in base 2)
                    const float sc = (which == 0) ? 0.125f * 1.44269504f : 1.0f;
                    *(__half2*)(dst + ((size_t)(bb0 * HH + hh) * TT + t0) * HD + dl) =
                        __floats2half2_rn(v00 * sc, v01 * sc);
                    *(__half2*)(dst + ((size_t)(bb1 * HH + hh) * TT + t1) * HD + dl) =
                        __floats2half2_rn(v10 * sc, v11 * sc);
                } else {
                    float2 lo, hi;
                    lo.x = v00; lo.y = v01;
                    hi.x = v10; hi.y = v11;
                    *(float2*)(out + (size_t)r_lo * NW + c) = lo;
                    *(float2*)(out + (size_t)(r_lo + 8) * NW + c) = hi;
                }
            }
        }
    }
}

// ---------------------------------------------------------------------------
// Flash attention (causal), fp16 mma + ldmatrix, base-2 online softmax
// (log2e folded into q scale; raw ex2.approx).
// 3-STAGE ring of 128-row K/V pair stages; two 64-row halves per barrier.
// Q (16KB) aliases stage-2 K half; Q frags hoisted at pr==0 before stage-2
// is first written. smem: 3 x 32768 = 98304 B. 2 CTAs/SM.
// ---------------------------------------------------------------------------
__global__ __launch_bounds__(256, 2) void attn_mma()
{
    extern __shared__ __align__(16) char smc[];
    const uint32_t sb = s2u(smc);
    const uint32_t sQ = sb + 65536;  // aliases stage-2 K half

    const int tid = threadIdx.x;
    const int lane = tid & 31;
    const int w = tid >> 5;
    const int g = lane >> 2, t4 = lane & 3;
    const int qt = 15 - (int)blockIdx.x;  // heavy tiles first
    const int h = blockIdx.y, b = blockIdx.z;

    const size_t ho = (size_t)(b * HH + h) * TT * HD;
    const __half* qb = g_q + ho;
    const __half* kb = g_k + ho;
    const __half* vb = g_v + ho;

    // stage = 128 K rows (16 KB) + 128 V rows (16 KB)
    auto issueKV = [&](int pr, int st) {
        const uint32_t base = sb + st * 32768;
#pragma unroll
        for (int r = 0; r < 4; ++r) {
            const int idx = tid + r * 256;
            const int m = idx >> 3, c = idx & 7;
            const uint32_t o = swz(m, c);
            cpa16(base + o, kb + (size_t)(pr * 128 + m) * HD + c * 8);
            cpa16(base + 16384 + o, vb + (size_t)(pr * 128 + m) * HD + c * 8);
        }
        cp_commit();
    };

    // Q tile into sQ, committed together with KV pair 0 (group 0)
#pragma unroll
    for (int r = 0; r < 4; ++r) {
        const int idx = tid + r * 256;
        const int m = idx >> 3, c = idx & 7;
        cpa16(sQ + swz(m, c), qb + (size_t)(qt * 128 + m) * HD + c * 8);
    }
    issueKV(0, 0);

    const int npairs = qt + 1;
    if (npairs > 1) issueKV(1, 1);

    float O[8][4];
#pragma unroll
    for (int n = 0; n < 8; ++n)
#pragma unroll
        for (int j = 0; j < 4; ++j) O[n][j] = 0.0f;
    float m_lo = -1e30f, m_hi = -1e30f, l_lo = 0.0f, l_hi = 0.0f;

    const int rlo = qt * 128 + w * 16 + g;

    // ldmatrix lane row/chunk decomposition
    const int qr = w * 16 + (lane & 15);
    const int qbit = lane >> 4;
    const int kr = (lane & 7) + ((lane >> 4) << 3);  // + np*16
    const int kbit = (lane >> 3) & 1;
    const int vr = lane & 15;                        // + 16*s
    const int vbit = (lane >> 4) & 1;

    uint32_t aq[4][4];  // Q fragments, hoisted

    for (int pr = 0; pr < npairs; ++pr) {
        if (pr + 1 < npairs) cp_wait<1>(); else cp_wait<0>();
        __syncthreads();
        if (pr == 0) {
            // Hoist Q fragments BEFORE stage-2 prefetch overwrites sQ.
#pragma unroll
            for (int s = 0; s < 4; ++s)
                ldm4(aq[s][0], aq[s][1], aq[s][2], aq[s][3],
                     sQ + swz(qr, 2 * s + qbit));
            if (npairs > 2) __syncthreads();  // all Q reads done before alias write
        }
        if (pr + 2 < npairs) issueKV(pr + 2, (pr + 2) % 3);
        const uint32_t stbase = sb + (pr % 3) * 32768;

#pragma unroll
        for (int half = 0; half < 2; ++half) {
            const int kt = 2 * pr + half;
            const uint32_t Ks = stbase + half * 8192;          // rows 64*half..
            const uint32_t Vs = stbase + 16384 + half * 8192;

            // S = Q K^T  (warp: 16 rows x 64 kv cols)
            float Sa[8][4];
#pragma unroll
            for (int n = 0; n < 8; ++n)
#pragma unroll
                for (int j = 0; j < 4; ++j) Sa[n][j] = 0.0f;

#pragma unroll
            for (int s = 0; s < 4; ++s) {
                uint32_t bk[8][2];
#pragma unroll
                for (int np = 0; np < 4; ++np) {
                    const int r = kr + np * 16;
                    ldm4(bk[2 * np][0], bk[2 * np][1], bk[2 * np + 1][0],
                         bk[2 * np + 1][1], Ks + swz(r, 2 * s + kbit));
                }
#pragma unroll
                for (int n = 0; n < 8; ++n)
                    mma16(Sa[n], aq[s][0], aq[s][1], aq[s][2], aq[s][3],
                          bk[n][0], bk[n][1]);
            }

            // causal mask (only the last two kv tiles cross the diagonal)
            if (kt >= 2 * qt) {
#pragma unroll
                for (int n = 0; n < 8; ++n) {
                    const int c = kt * 64 + n * 8 + t4 * 2;
                    if (c > rlo) Sa[n][0] = -1e30f;
                    if (c + 1 > rlo) Sa[n][1] = -1e30f;
                    if (c > rlo + 8) Sa[n][2] = -1e30f;
                    if (c + 1 > rlo + 8) Sa[n][3] = -1e30f;
                }
            }

            // online softmax in base 2 (rows g, g+8; quad reduction)
            float mx_lo = -1e30f, mx_hi = -1e30f;
#pragma unroll
            for (int n = 0; n < 8; ++n) {
                mx_lo = fmaxf(mx_lo, fmaxf(Sa[n][0], Sa[n][1]));
                mx_hi = fmaxf(mx_hi, fmaxf(Sa[n][2], Sa[n][3]));
            }
            mx_lo = fmaxf(mx_lo, __shfl_xor_sync(0xffffffffu, mx_lo, 1));
            mx_lo = fmaxf(mx_lo, __shfl_xor_sync(0xffffffffu, mx_lo, 2));
            mx_hi = fmaxf(mx_hi, __shfl_xor_sync(0xffffffffu, mx_hi, 1));
            mx_hi = fmaxf(mx_hi, __shfl_xor_sync(0xffffffffu, mx_hi, 2));
            const float mn_lo = fmaxf(m_lo, mx_lo);
            const float mn_hi = fmaxf(m_hi, mx_hi);
            const float al_lo = ex2f(m_lo - mn_lo);
            const float al_hi = ex2f(m_hi - mn_hi);
            m_lo = mn_lo;
            m_hi = mn_hi;
            float rs_lo = 0.0f, rs_hi = 0.0f;
#pragma unroll
            for (int n = 0; n < 8; ++n) {
                Sa[n][0] = ex2f(Sa[n][0] - mn_lo);
                Sa[n][1] = ex2f(Sa[n][1] - mn_lo);
                Sa[n][2] = ex2f(Sa[n][2] - mn_hi);
                Sa[n][3] = ex2f(Sa[n][3] - mn_hi);
                rs_lo += Sa[n][0] + Sa[n][1];
                rs_hi += Sa[n][2] + Sa[n][3];
            }
            rs_lo += __shfl_xor_sync(0xffffffffu, rs_lo, 1);
            rs_lo += __shfl_xor_sync(0xffffffffu, rs_lo, 2);
            rs_hi += __shfl_xor_sync(0xffffffffu, rs_hi, 1);
            rs_hi += __shfl_xor_sync(0xffffffffu, rs_hi, 2);
            l_lo = l_lo * al_lo + rs_lo;
            l_hi = l_hi * al_hi + rs_hi;
#pragma unroll
            for (int n = 0; n < 8; ++n) {
                O[n][0] *= al_lo;
                O[n][1] *= al_lo;
                O[n][2] *= al_hi;
                O[n][3] *= al_hi;
            }

            // O += P V : P a-frags directly from S c-frag pairs (fp16 pack)
#pragma unroll
            for (int s = 0; s < 4; ++s) {
                const uint32_t pa0 = packh2(Sa[2 * s][0], Sa[2 * s][1]);
                const uint32_t pa1 = packh2(Sa[2 * s][2], Sa[2 * s][3]);
                const uint32_t pa2 = packh2(Sa[2 * s + 1][0], Sa[2 * s + 1][1]);
                const uint32_t pa3 = packh2(Sa[2 * s + 1][2], Sa[2 * s + 1][3]);
                uint32_t bv[8][2];
#pragma unroll
                for (int vp = 0; vp < 4; ++vp) {
                    const int r = 16 * s + vr;
                    ldm4t(bv[2 * vp][0], bv[2 * vp][1], bv[2 * vp + 1][0],
                          bv[2 * vp + 1][1], Vs + swz(r, 2 * vp + vbit));
                }
#pragma unroll
                for (int n = 0; n < 8; ++n)
                    mma16(O[n], pa0, pa1, pa2, pa3, bv[n][0], bv[n][1]);
            }
        }
    }

    // write y [B,T,C] half
    const float inv_lo = 1.0f / l_lo;
    const float inv_hi = 1.0f / l_hi;
    __half* y0 = g_y + (size_t)(b * TT + rlo) * CC;
    __half* y1 = g_y + (size_t)(b * TT + rlo + 8) * CC;
#pragma unroll
    for (int n = 0; n < 8; ++n) {
        const int c = h * HD + n * 8 + t4 * 2;
        *(__half2*)(y0 + c) = __floats2half2_rn(O[n][0] * inv_lo, O[n][1] * inv_lo);
        *(__half2*)(y1 + c) = __floats2half2_rn(O[n][2] * inv_hi, O[n][3] * inv_hi);
    }
}

// ---------------------------------------------------------------------------
extern "C" void kernel_launch(void* const* d_in, const int* in_sizes, int n_in,
                              void* d_out, int out_size)
{
    (void)in_sizes; (void)n_in; (void)out_size;
    const float* x      = (const float*)d_in[0];
    const float* W_attn = (const float*)d_in[1];
    const float* b_attn = (const float*)d_in[2];
    const float* W_proj = (const float*)d_in[3];
    const float* b_proj = (const float*)d_in[4];
    float* out = (float*)d_out;

    const int smem_gemm = 3 * 32768;  // 98304 B
    const int smem_attn = 3 * 32768;  // 98304 B (Q aliases stage 2)
    cudaFuncSetAttribute((const void*)gemm_mma<0, 3072, 768, 24>,
                         cudaFuncAttributeMaxDynamicSharedMemorySize, smem_gemm);
    cudaFuncSetAttribute((const void*)gemm_mma<1, 1024, 256, 8>,
                         cudaFuncAttributeMaxDynamicSharedMemorySize, smem_gemm);
    cudaFuncSetAttribute((const void*)attn_mma,
                         cudaFuncAttributeMaxDynamicSharedMemorySize, smem_attn);

    // 0) convert inputs to half (+ transpose W)
    prep_x<<<(BB * TT * CC / 4) / 256, 256>>>(x);
    prep_w<<<dim3(3072 / 32, 1024 / 32), dim3(32, 8)>>>(W_attn, 3072, 0);
    prep_w<<<dim3(1024 / 32, 1024 / 32), dim3(32, 8)>>>(W_proj, 1024, 1);

    // 1) QKV GEMM + bias -> q/k/v (half): persistent, 296 CTAs over 768 tiles
    gemm_mma<0, 3072, 768, 24><<<296, 256, smem_gemm>>>(b_attn, nullptr);

    // 2) causal flash attention -> g_y (half)
    attn_mma<<<dim3(16, HH, BB), 256, smem_attn>>>();

    // 3) output projection + bias -> out (f32): 256 tiles, single wave
    gemm_mma<1, 1024, 256, 8><<<256, 256, smem_gemm>>>(b_proj, out);
}